// round 5
// baseline (speedup 1.0000x reference)
#include <cuda_runtime.h>

#define NN 512
#define TP 16

typedef unsigned long long ull;

// ---------- f32x2 packed helpers (FFMA2: 2x fp32 rate, only reachable via PTX) ----------
__device__ __forceinline__ ull pk2(float lo, float hi) {
    ull r; asm("mov.b64 %0, {%1, %2};" : "=l"(r) : "f"(lo), "f"(hi)); return r;
}
__device__ __forceinline__ void upk2(float& lo, float& hi, ull v) {
    asm("mov.b64 {%0, %1}, %2;" : "=f"(lo), "=f"(hi) : "l"(v));
}
__device__ __forceinline__ void ffma2(ull& acc, ull a, ull b) {
    asm("fma.rn.f32x2 %0, %1, %2, %0;" : "+l"(acc) : "l"(a), "l"(b));
}

// ---------------- scratch ----------------
__device__ float g_XW1a[NN * TP * 32];
__device__ float g_XW1b[NN * TP * 32];
__device__ float g_XW2a[NN * TP * 32];
__device__ float g_XW2b[NN * TP * 32];
__device__ float g_Q[NN * 32];
__device__ float g_QB[NN * TP];
__device__ float g_RA[NN * TP];
__device__ float g_L1[NN * NN];    // logits1 -> s1
__device__ float g_L2T[NN * NN];   // logits2^T -> s2^T
__device__ float g_r1[NN * TP];
__device__ float g_c2[NN * TP];
__device__ float g_acc[NN * 32];

// ---------------- k1: XW1a/b, XW2a/b, Q, QB, RA ----------------
__global__ void k1_precompute(const float* __restrict__ x,
                              const float* __restrict__ W1,
                              const float* __restrict__ W2,
                              const float* __restrict__ W3) {
    int n0 = blockIdx.x * 4;
    __shared__ float xs[4][16];
    int tid = threadIdx.x;
    if (tid < 64) xs[tid / 16][tid % 16] = x[(n0 + tid / 16) * 16 + (tid % 16)];
    __syncthreads();

    for (int th = tid; th < 512; th += 256) {
        float a1[4] = {0,0,0,0}, b1[4] = {0,0,0,0};
        float a2[4] = {0,0,0,0}, b2[4] = {0,0,0,0};
        for (int i = 0; i < 16; i++) {
            float w1a = W1[i * 512 + th];
            float w1b = W1[(i + 16) * 512 + th];
            float w2a = W2[i * 512 + th];
            float w2b = W2[(i + 16) * 512 + th];
#pragma unroll
            for (int j = 0; j < 4; j++) {
                float xv = xs[j][i];
                a1[j] += xv * w1a; b1[j] += xv * w1b;
                a2[j] += xv * w2a; b2[j] += xv * w2b;
            }
        }
#pragma unroll
        for (int j = 0; j < 4; j++) {
            g_XW1a[(n0 + j) * 512 + th] = a1[j];
            g_XW1b[(n0 + j) * 512 + th] = b1[j];
            g_XW2a[(n0 + j) * 512 + th] = a2[j];
            g_XW2b[(n0 + j) * 512 + th] = b2[j];
        }
    }
    if (tid < 32) {
#pragma unroll
        for (int j = 0; j < 4; j++) {
            float acc = 0.f;
            for (int i = 0; i < 16; i++) acc += xs[j][i] * W3[i * 32 + tid];
            g_Q[(n0 + j) * 32 + tid] = acc;
        }
    }
    __syncthreads();
    if (tid < 64) {
        int n = n0 + tid / 16, t = tid % 16;
        const float* q  = g_Q + n * 32;
        const float* wa = g_XW1a + n * 512 + t * 32;
        const float* wb = g_XW1b + n * 512 + t * 32;
        float ra = 0.f, qb = 0.f;
#pragma unroll
        for (int h = 0; h < 32; h++) { float qv = q[h]; ra += qv * wa[h]; qb += qv * wb[h]; }
        g_RA[n * 16 + t] = ra;
        g_QB[n * 16 + t] = qb;
    }
}

// ---------------- k2: fused logits + zero accumulators ----------------
__global__ void __launch_bounds__(512) k2_logits(const float* __restrict__ adj) {
    int tid = threadIdx.x;
    int bid = blockIdx.y * 16 + blockIdx.x;
    if (bid < 32)      g_acc[bid * 512 + tid] = 0.f;
    else if (bid < 48) g_r1[(bid - 32) * 512 + tid] = 0.f;
    else if (bid < 64) g_c2[(bid - 48) * 512 + tid] = 0.f;

    int a0 = blockIdx.y * 32, b0 = blockIdx.x * 32;
    int bl = tid >> 4, t = tid & 15;
    int bg = b0 + bl;

    __shared__ ull   Qs[32][16];
    __shared__ float QBs[32][16], RAs[32][16];
    {
        int a = tid >> 4, p = tid & 15;
        float2 v = *((const float2*)(g_Q + (a0 + a) * 32) + p);
        Qs[a][p]  = pk2(v.x, v.y);
        QBs[a][p] = g_QB[(a0 + a) * 16 + p];
        RAs[a][p] = g_RA[(a0 + a) * 16 + p];
    }
    ull wa[16], wb[16];
    {
        const float4* pa = (const float4*)(g_XW1a + (bg * 16 + t) * 32);
        const float4* pb = (const float4*)(g_XW1b + (bg * 16 + t) * 32);
#pragma unroll
        for (int v = 0; v < 8; v++) {
            float4 fa = pa[v], fb = pb[v];
            wa[2 * v] = pk2(fa.x, fa.y); wa[2 * v + 1] = pk2(fa.z, fa.w);
            wb[2 * v] = pk2(fb.x, fb.y); wb[2 * v + 1] = pk2(fb.z, fb.w);
        }
    }
    __syncthreads();

    bool hasT = (t < 15);
    const float* pR = adj + ((long)a0 * 512 + bg) * 15 + t;
    const float* pC = adj + ((long)bg * 512 + a0) * 15 + t;

    // software-pipelined adj loads (break LDG->use latency chain)
    float arN = 0.f, acN = 0.f;
    if (hasT) { arN = __ldg(pR); acN = __ldg(pC); }

    for (int al = 0; al < 32; al++) {
        float ar = arN, ac = acN;
        if (hasT && al < 31) {
            arN = __ldg(pR + (al + 1) * 7680);
            acN = __ldg(pC + (al + 1) * 15);
        }
        int ag = a0 + al;
        ull acc1 = 0ull, acc2 = 0ull;
        const ulonglong2* qrow = (const ulonglong2*)Qs[al];
#pragma unroll
        for (int j = 0; j < 8; j++) {
            ulonglong2 q = qrow[j];
            ffma2(acc1, q.x, wa[2 * j]);
            ffma2(acc1, q.y, wa[2 * j + 1]);
            ffma2(acc2, q.x, wb[2 * j]);
            ffma2(acc2, q.y, wb[2 * j + 1]);
        }
        float lo, hi;
        upk2(lo, hi, acc1); float p1 = lo + hi;
        upk2(lo, hi, acc2); float p2 = lo + hi;

        float l1p, l2p;
        if (hasT) {
            l1p = ar * p1 + ac * QBs[al][t];
            l2p = ac * RAs[al][t] + ar * p2;
        } else {
            bool dg = (ag == bg);
            l1p = dg ? (p1 + QBs[al][15]) : 0.f;
            l2p = dg ? (RAs[al][15] + p2) : 0.f;
        }
        // packed dual reduction: 5 shfl instead of 8
        float u = l1p + __shfl_xor_sync(0xffffffffu, l1p, 8);
        float v = l2p + __shfl_xor_sync(0xffffffffu, l2p, 8);
        float w = (t & 8) ? v : u;
        w += __shfl_xor_sync(0xffffffffu, w, 4);
        w += __shfl_xor_sync(0xffffffffu, w, 2);
        w += __shfl_xor_sync(0xffffffffu, w, 1);
        if (t == 0) g_L1[ag * 512 + bg]  = w;
        if (t == 8) g_L2T[ag * 512 + bg] = w;
    }
}

// ---------------- k5: row softmax ----------------
__global__ void k5_softmax() {
    int r = blockIdx.x;
    float* row = (r < 512) ? (g_L1 + r * 512) : (g_L2T + (r - 512) * 512);
    int tid = threadIdx.x;
    __shared__ float red[8];
    float v0 = row[tid], v1 = row[tid + 256];
    float m = fmaxf(v0, v1);
#pragma unroll
    for (int o = 16; o; o >>= 1) m = fmaxf(m, __shfl_xor_sync(0xffffffffu, m, o));
    if ((tid & 31) == 0) red[tid >> 5] = m;
    __syncthreads();
    float bm = red[0];
#pragma unroll
    for (int i = 1; i < 8; i++) bm = fmaxf(bm, red[i]);
    float e0 = __expf(v0 - bm), e1 = __expf(v1 - bm);
    float s = e0 + e1;
#pragma unroll
    for (int o = 16; o; o >>= 1) s += __shfl_xor_sync(0xffffffffu, s, o);
    __syncthreads();
    if ((tid & 31) == 0) red[tid >> 5] = s;
    __syncthreads();
    float bs = red[0] + red[1] + red[2] + red[3] + red[4] + red[5] + red[6] + red[7];
    float inv = 1.0f / bs;
    row[tid] = e0 * inv;
    row[tid + 256] = e1 * inv;
}

// ---------------- k7: split-variant fused A-build + 8a x 8d register GEMM ----------------
// grid (16 m-tiles, 16 a-tiles, 2 variants), 256 threads.
struct K7S {
    ull   Asp[128][16];    // packed a-pairs       16KB
    float Bs[128][32];     //                      16KB
    float ss[32][33];
    float adjS[32][121];
    float accS[32][32];
};

__global__ void __launch_bounds__(256, 2) k7_fused(const float* __restrict__ adj) {
    extern __shared__ char smem_raw[];
    K7S& S = *reinterpret_cast<K7S*>(smem_raw);
    int m0 = blockIdx.x * 32;
    int a0 = blockIdx.y * 32;
    int var = blockIdx.z;
    int tid = threadIdx.x;

    const float* sSrc = var ? g_L2T : g_L1;
    const float* bSrc = var ? g_XW2b : g_XW2a;
    float* rcDst      = var ? g_c2 : g_r1;

#pragma unroll
    for (int j = 0; j < 4; j++) {
        int idx = tid + j * 256;
        int a = idx >> 5, ml = idx & 31;
        S.ss[a][ml] = sSrc[(a0 + a) * 512 + m0 + ml];
        S.accS[a][ml] = 0.f;
    }
    __syncthreads();

    // r1/c2 partials over this block's m-range
    {
        int a = tid >> 3, tp = tid & 7;
        int t0 = tp * 2;
        int ag = a0 + a;
        bool hasT1 = (t0 + 1 < 15);
        float r0 = 0.f, r1v = 0.f;
        for (int ml = 0; ml < 32; ml++) {
            const float* base = adj + ((long)(m0 + ml) * 512 + ag) * 15;
            float v0 = base[t0];
            float v1 = hasT1 ? base[t0 + 1] : 0.f;
            float w = S.ss[a][ml];
            r0 += w * v0; r1v += w * v1;
        }
        atomicAdd(&rcDst[ag * 16 + t0], r0);
        if (hasT1) {
            atomicAdd(&rcDst[ag * 16 + t0 + 1], r1v);
        } else if (ag >= m0 && ag < m0 + 32) {
            atomicAdd(&rcDst[ag * 16 + 15], S.ss[a][ag - m0]);
        }
    }

    // thread tile: 8a x 8d, 16-way k-split within block
    int pos = tid & 15, ksub = tid >> 4;
    int pa4 = (pos & 3) * 4;        // base a-pair (4 pairs = 8 a)
    int d8  = (pos >> 2) * 8;       // base d
    ull acc[4][8];
#pragma unroll
    for (int p = 0; p < 4; p++)
#pragma unroll
        for (int j = 0; j < 8; j++) acc[p][j] = 0ull;

    for (int mc = 0; mc < 4; mc++) {
        int mb = m0 + mc * 8;
        __syncthreads();
        // stage adj rows: 32 a x 120 contiguous floats
        for (int idx = tid; idx < 960; idx += 256) {
            int a = idx / 30, r4 = (idx - a * 30) * 4;
            float4 v = *(const float4*)(adj + (long)(a0 + a) * 7680 + mb * 15 + r4);
            float* dst = &S.adjS[a][r4];
            dst[0] = v.x; dst[1] = v.y; dst[2] = v.z; dst[3] = v.w;
        }
        // stage B panel (float4)
        for (int idx = tid; idx < 1024; idx += 256) {
            int kk = idx >> 3, dd = (idx & 7) * 4;
            *(float4*)&S.Bs[kk][dd] = *(const float4*)(bSrc + (mb * 16 + kk) * 32 + dd);
        }
        __syncthreads();
        // build packed A tile
#pragma unroll
        for (int j = 0; j < 8; j++) {
            int idx = tid + j * 256;
            int ap = idx & 15, kk = idx >> 4;
            int ml = kk >> 4, t = kk & 15;
            float v[2];
#pragma unroll
            for (int l = 0; l < 2; l++) {
                int a = 2 * ap + l;
                float sv = S.ss[a][mc * 8 + ml];
                if (t < 15) {
                    v[l] = sv * S.adjS[a][ml * 15 + t];
                } else {
                    v[l] = (mb + ml == a0 + a) ? sv : 0.f;
                }
            }
            S.Asp[kk][ap] = pk2(v[0], v[1]);
        }
        __syncthreads();
        // inner: 8 kk per thread
        int kk0 = ksub * 8;
#pragma unroll
        for (int i = 0; i < 8; i++) {
            int kk = kk0 + i;
            ulonglong2 A01 = *(const ulonglong2*)&S.Asp[kk][pa4];
            ulonglong2 A23 = *(const ulonglong2*)&S.Asp[kk][pa4 + 2];
            float4 b0 = *(const float4*)&S.Bs[kk][d8];
            float4 b1 = *(const float4*)&S.Bs[kk][d8 + 4];
            ull bd[8];
            bd[0] = pk2(b0.x, b0.x); bd[1] = pk2(b0.y, b0.y);
            bd[2] = pk2(b0.z, b0.z); bd[3] = pk2(b0.w, b0.w);
            bd[4] = pk2(b1.x, b1.x); bd[5] = pk2(b1.y, b1.y);
            bd[6] = pk2(b1.z, b1.z); bd[7] = pk2(b1.w, b1.w);
#pragma unroll
            for (int j = 0; j < 8; j++) {
                ffma2(acc[0][j], A01.x, bd[j]);
                ffma2(acc[1][j], A01.y, bd[j]);
                ffma2(acc[2][j], A23.x, bd[j]);
                ffma2(acc[3][j], A23.y, bd[j]);
            }
        }
    }

    // merge 16 k-split partials via shared atomics
    __syncthreads();
#pragma unroll
    for (int p = 0; p < 4; p++) {
        int aa = 2 * (pa4 + p);
#pragma unroll
        for (int j = 0; j < 8; j++) {
            float lo, hi; upk2(lo, hi, acc[p][j]);
            atomicAdd(&S.accS[aa][d8 + j], lo);
            atomicAdd(&S.accS[aa + 1][d8 + j], hi);
        }
    }
    __syncthreads();
    for (int idx = tid; idx < 1024; idx += 256) {
        int aa = idx >> 5, dd = idx & 31;
        atomicAdd(&g_acc[(a0 + aa) * 32 + dd], S.accS[aa][dd]);
    }
}

// ---------------- k7b: epilogue ----------------
__global__ void k7b_epilogue(float* __restrict__ out) {
    int idx = blockIdx.x * 256 + threadIdx.x;
    int n = idx >> 5, d = idx & 31;
    float acc = g_acc[idx];
    const float* r1 = g_r1 + n * 16;
    const float* c2 = g_c2 + n * 16;
    const float* wb = g_XW2b + n * 512 + d;
    const float* wa = g_XW2a + n * 512 + d;
#pragma unroll
    for (int t = 0; t < 16; t++) acc += r1[t] * wb[t * 32] + c2[t] * wa[t * 32];
    out[idx] = fmaxf(acc, 0.2f * acc);
}

// ---------------- launch ----------------
extern "C" void kernel_launch(void* const* d_in, const int* in_sizes, int n_in,
                              void* d_out, int out_size) {
    const float* x   = (const float*)d_in[0];
    const float* adj = (const float*)d_in[1];
    const float* W1  = (const float*)d_in[2];
    const float* W2  = (const float*)d_in[3];
    const float* W3  = (const float*)d_in[4];
    float* out = (float*)d_out;
    (void)in_sizes; (void)n_in; (void)out_size;

    cudaFuncSetAttribute(k7_fused, cudaFuncAttributeMaxDynamicSharedMemorySize,
                         (int)sizeof(K7S));

    k1_precompute<<<128, 256>>>(x, W1, W2, W3);
    k2_logits<<<dim3(16, 16), 512>>>(adj);
    k5_softmax<<<1024, 256>>>();
    k7_fused<<<dim3(16, 16, 2), 256, sizeof(K7S)>>>(adj);
    k7b_epilogue<<<64, 256>>>(out);
}

// round 6
// speedup vs baseline: 1.2563x; 1.2563x over previous
#include <cuda_runtime.h>

#define NN 512
#define TP 16

typedef unsigned long long ull;

// ---------- f32x2 packed helpers (FFMA2: 2x fp32 rate, only reachable via PTX) ----------
__device__ __forceinline__ ull pk2(float lo, float hi) {
    ull r; asm("mov.b64 %0, {%1, %2};" : "=l"(r) : "f"(lo), "f"(hi)); return r;
}
__device__ __forceinline__ void upk2(float& lo, float& hi, ull v) {
    asm("mov.b64 {%0, %1}, %2;" : "=f"(lo), "=f"(hi) : "l"(v));
}
__device__ __forceinline__ void ffma2(ull& acc, ull a, ull b) {
    asm("fma.rn.f32x2 %0, %1, %2, %0;" : "+l"(acc) : "l"(a), "l"(b));
}

// ---------------- scratch ----------------
__device__ float g_XW1a[NN * TP * 32];
__device__ float g_XW1b[NN * TP * 32];
__device__ float g_XW2a[NN * TP * 32];
__device__ float g_XW2b[NN * TP * 32];
__device__ float g_Q[NN * 32];
__device__ float g_QB[NN * TP];
__device__ float g_RA[NN * TP];
__device__ float g_L1[NN * NN];    // logits1 -> s1
__device__ float g_L2T[NN * NN];   // logits2^T -> s2^T
__device__ float g_r1[NN * TP];
__device__ float g_c2[NN * TP];
__device__ float g_acc[NN * 32];
__device__ int   g_ctr[16];        // per-a-tile completion counters

// ---------------- k1: XW1a/b, XW2a/b, Q, QB, RA ----------------
__global__ void k1_precompute(const float* __restrict__ x,
                              const float* __restrict__ W1,
                              const float* __restrict__ W2,
                              const float* __restrict__ W3) {
    int n0 = blockIdx.x * 4;
    __shared__ float xs[4][16];
    int tid = threadIdx.x;
    if (tid < 64) xs[tid / 16][tid % 16] = x[(n0 + tid / 16) * 16 + (tid % 16)];
    __syncthreads();

    for (int th = tid; th < 512; th += 256) {
        float a1[4] = {0,0,0,0}, b1[4] = {0,0,0,0};
        float a2[4] = {0,0,0,0}, b2[4] = {0,0,0,0};
        for (int i = 0; i < 16; i++) {
            float w1a = W1[i * 512 + th];
            float w1b = W1[(i + 16) * 512 + th];
            float w2a = W2[i * 512 + th];
            float w2b = W2[(i + 16) * 512 + th];
#pragma unroll
            for (int j = 0; j < 4; j++) {
                float xv = xs[j][i];
                a1[j] += xv * w1a; b1[j] += xv * w1b;
                a2[j] += xv * w2a; b2[j] += xv * w2b;
            }
        }
#pragma unroll
        for (int j = 0; j < 4; j++) {
            g_XW1a[(n0 + j) * 512 + th] = a1[j];
            g_XW1b[(n0 + j) * 512 + th] = b1[j];
            g_XW2a[(n0 + j) * 512 + th] = a2[j];
            g_XW2b[(n0 + j) * 512 + th] = b2[j];
        }
    }
    if (tid < 32) {
#pragma unroll
        for (int j = 0; j < 4; j++) {
            float acc = 0.f;
            for (int i = 0; i < 16; i++) acc += xs[j][i] * W3[i * 32 + tid];
            g_Q[(n0 + j) * 32 + tid] = acc;
        }
    }
    __syncthreads();
    if (tid < 64) {
        int n = n0 + tid / 16, t = tid % 16;
        const float* q  = g_Q + n * 32;
        const float* wa = g_XW1a + n * 512 + t * 32;
        const float* wb = g_XW1b + n * 512 + t * 32;
        float ra = 0.f, qb = 0.f;
#pragma unroll
        for (int h = 0; h < 32; h++) { float qv = q[h]; ra += qv * wa[h]; qb += qv * wb[h]; }
        g_RA[n * 16 + t] = ra;
        g_QB[n * 16 + t] = qb;
    }
}

// ---------------- k2: fused logits + zero accumulators/counters ----------------
__global__ void __launch_bounds__(512) k2_logits(const float* __restrict__ adj) {
    int tid = threadIdx.x;
    int bid = blockIdx.y * 16 + blockIdx.x;
    if (bid < 32)      g_acc[bid * 512 + tid] = 0.f;
    else if (bid < 48) g_r1[(bid - 32) * 512 + tid] = 0.f;
    else if (bid < 64) g_c2[(bid - 48) * 512 + tid] = 0.f;
    else if (bid == 64 && tid < 16) g_ctr[tid] = 0;

    int a0 = blockIdx.y * 32, b0 = blockIdx.x * 32;
    int bl = tid >> 4, t = tid & 15;
    int bg = b0 + bl;

    __shared__ ull   Qs[32][16];
    __shared__ float QBs[32][16], RAs[32][16];
    {
        int a = tid >> 4, p = tid & 15;
        float2 v = *((const float2*)(g_Q + (a0 + a) * 32) + p);
        Qs[a][p]  = pk2(v.x, v.y);
        QBs[a][p] = g_QB[(a0 + a) * 16 + p];
        RAs[a][p] = g_RA[(a0 + a) * 16 + p];
    }
    ull wa[16], wb[16];
    {
        const float4* pa = (const float4*)(g_XW1a + (bg * 16 + t) * 32);
        const float4* pb = (const float4*)(g_XW1b + (bg * 16 + t) * 32);
#pragma unroll
        for (int v = 0; v < 8; v++) {
            float4 fa = pa[v], fb = pb[v];
            wa[2 * v] = pk2(fa.x, fa.y); wa[2 * v + 1] = pk2(fa.z, fa.w);
            wb[2 * v] = pk2(fb.x, fb.y); wb[2 * v + 1] = pk2(fb.z, fb.w);
        }
    }
    __syncthreads();

    bool hasT = (t < 15);
    const float* pR = adj + ((long)a0 * 512 + bg) * 15 + t;
    const float* pC = adj + ((long)bg * 512 + a0) * 15 + t;

    // software-pipelined adj loads (break LDG->use latency chain)
    float arN = 0.f, acN = 0.f;
    if (hasT) { arN = __ldg(pR); acN = __ldg(pC); }

    for (int al = 0; al < 32; al++) {
        float ar = arN, ac = acN;
        if (hasT && al < 31) {
            arN = __ldg(pR + (al + 1) * 7680);
            acN = __ldg(pC + (al + 1) * 15);
        }
        int ag = a0 + al;
        ull acc1 = 0ull, acc2 = 0ull;
        const ulonglong2* qrow = (const ulonglong2*)Qs[al];
#pragma unroll
        for (int j = 0; j < 8; j++) {
            ulonglong2 q = qrow[j];
            ffma2(acc1, q.x, wa[2 * j]);
            ffma2(acc1, q.y, wa[2 * j + 1]);
            ffma2(acc2, q.x, wb[2 * j]);
            ffma2(acc2, q.y, wb[2 * j + 1]);
        }
        float lo, hi;
        upk2(lo, hi, acc1); float p1 = lo + hi;
        upk2(lo, hi, acc2); float p2 = lo + hi;

        float l1p, l2p;
        if (hasT) {
            l1p = ar * p1 + ac * QBs[al][t];
            l2p = ac * RAs[al][t] + ar * p2;
        } else {
            bool dg = (ag == bg);
            l1p = dg ? (p1 + QBs[al][15]) : 0.f;
            l2p = dg ? (RAs[al][15] + p2) : 0.f;
        }
        // packed dual reduction: 5 shfl instead of 8
        float u = l1p + __shfl_xor_sync(0xffffffffu, l1p, 8);
        float v = l2p + __shfl_xor_sync(0xffffffffu, l2p, 8);
        float w = (t & 8) ? v : u;
        w += __shfl_xor_sync(0xffffffffu, w, 4);
        w += __shfl_xor_sync(0xffffffffu, w, 2);
        w += __shfl_xor_sync(0xffffffffu, w, 1);
        if (t == 0) g_L1[ag * 512 + bg]  = w;
        if (t == 8) g_L2T[ag * 512 + bg] = w;
    }
}

// ---------------- k5: row softmax ----------------
__global__ void k5_softmax() {
    int r = blockIdx.x;
    float* row = (r < 512) ? (g_L1 + r * 512) : (g_L2T + (r - 512) * 512);
    int tid = threadIdx.x;
    __shared__ float red[8];
    float v0 = row[tid], v1 = row[tid + 256];
    float m = fmaxf(v0, v1);
#pragma unroll
    for (int o = 16; o; o >>= 1) m = fmaxf(m, __shfl_xor_sync(0xffffffffu, m, o));
    if ((tid & 31) == 0) red[tid >> 5] = m;
    __syncthreads();
    float bm = red[0];
#pragma unroll
    for (int i = 1; i < 8; i++) bm = fmaxf(bm, red[i]);
    float e0 = __expf(v0 - bm), e1 = __expf(v1 - bm);
    float s = e0 + e1;
#pragma unroll
    for (int o = 16; o; o >>= 1) s += __shfl_xor_sync(0xffffffffu, s, o);
    __syncthreads();
    if ((tid & 31) == 0) red[tid >> 5] = s;
    __syncthreads();
    float bs = red[0] + red[1] + red[2] + red[3] + red[4] + red[5] + red[6] + red[7];
    float inv = 1.0f / bs;
    row[tid] = e0 * inv;
    row[tid + 256] = e1 * inv;
}

// ---------------- k7: split-variant fused A-build + 4a x 4d GEMM + fused epilogue ----------------
// grid (16 m-tiles, 16 a-tiles, 2 variants), 256 threads.
struct K7S {
    ull   Asp[128][16];    // packed a-pairs
    float Bs[128][32];
    float ss[32][33];
    float adjS[32][121];
    float accS[32][33];
};

__global__ void __launch_bounds__(256) k7_fused(const float* __restrict__ adj,
                                                float* __restrict__ out) {
    extern __shared__ char smem_raw[];
    K7S& S = *reinterpret_cast<K7S*>(smem_raw);
    int m0 = blockIdx.x * 32;
    int a0 = blockIdx.y * 32;
    int var = blockIdx.z;
    int tid = threadIdx.x;

    const float* sSrc = var ? g_L2T : g_L1;
    const float* bSrc = var ? g_XW2b : g_XW2a;
    float* rcDst      = var ? g_c2 : g_r1;

#pragma unroll
    for (int j = 0; j < 4; j++) {
        int idx = tid + j * 256;
        int a = idx >> 5, ml = idx & 31;
        S.ss[a][ml] = sSrc[(a0 + a) * 512 + m0 + ml];
    }
    __syncthreads();

    // r1/c2 partials over this block's m-range
    {
        int a = tid >> 3, tp = tid & 7;
        int t0 = tp * 2;
        int ag = a0 + a;
        bool hasT1 = (t0 + 1 < 15);
        float r0 = 0.f, r1v = 0.f;
        for (int ml = 0; ml < 32; ml++) {
            const float* base = adj + ((long)(m0 + ml) * 512 + ag) * 15;
            float v0 = base[t0];
            float v1 = hasT1 ? base[t0 + 1] : 0.f;
            float w = S.ss[a][ml];
            r0 += w * v0; r1v += w * v1;
        }
        atomicAdd(&rcDst[ag * 16 + t0], r0);
        if (hasT1) {
            atomicAdd(&rcDst[ag * 16 + t0 + 1], r1v);
        } else if (ag >= m0 && ag < m0 + 32) {
            atomicAdd(&rcDst[ag * 16 + 15], S.ss[a][ag - m0]);
        }
    }

    // thread tile: 4a x 4d, 4-way k-split within block
    int pos = tid & 63, ksub = tid >> 6;
    int a4 = (pos & 7) * 4;
    int d4 = (pos >> 3) * 4;
    ull acc[2][4];
#pragma unroll
    for (int p = 0; p < 2; p++)
#pragma unroll
        for (int j = 0; j < 4; j++) acc[p][j] = 0ull;

    for (int mc = 0; mc < 4; mc++) {
        int mb = m0 + mc * 8;
        __syncthreads();
        // stage adj rows: 32 a x 120 contiguous floats
        for (int idx = tid; idx < 960; idx += 256) {
            int a = idx / 30, r4 = (idx - a * 30) * 4;
            float4 v = *(const float4*)(adj + (long)(a0 + a) * 7680 + mb * 15 + r4);
            float* dst = &S.adjS[a][r4];
            dst[0] = v.x; dst[1] = v.y; dst[2] = v.z; dst[3] = v.w;
        }
        // stage B panel (float4)
        for (int idx = tid; idx < 1024; idx += 256) {
            int kk = idx >> 3, dd = (idx & 7) * 4;
            *(float4*)&S.Bs[kk][dd] = *(const float4*)(bSrc + (mb * 16 + kk) * 32 + dd);
        }
        __syncthreads();
        // build packed A tile
#pragma unroll
        for (int j = 0; j < 8; j++) {
            int idx = tid + j * 256;
            int ap = idx & 15, kk = idx >> 4;
            int ml = kk >> 4, t = kk & 15;
            float v[2];
#pragma unroll
            for (int l = 0; l < 2; l++) {
                int a = 2 * ap + l;
                float sv = S.ss[a][mc * 8 + ml];
                if (t < 15) {
                    v[l] = sv * S.adjS[a][ml * 15 + t];
                } else {
                    v[l] = (mb + ml == a0 + a) ? sv : 0.f;
                }
            }
            S.Asp[kk][ap] = pk2(v[0], v[1]);
        }
        __syncthreads();
        // inner: 32 kk per thread
        int kk0 = ksub * 32;
        const ull*   pA = &S.Asp[0][(pos & 7) * 2];
        const float* pB = &S.Bs[0][d4];
#pragma unroll 8
        for (int kk = kk0; kk < kk0 + 32; kk++) {
            ulonglong2 A = *(const ulonglong2*)(pA + kk * 16);
            float4 b = *(const float4*)(pB + kk * 32);
            ull bx = pk2(b.x, b.x), by = pk2(b.y, b.y);
            ull bz = pk2(b.z, b.z), bw = pk2(b.w, b.w);
            ffma2(acc[0][0], A.x, bx); ffma2(acc[0][1], A.x, by);
            ffma2(acc[0][2], A.x, bz); ffma2(acc[0][3], A.x, bw);
            ffma2(acc[1][0], A.y, bx); ffma2(acc[1][1], A.y, by);
            ffma2(acc[1][2], A.y, bz); ffma2(acc[1][3], A.y, bw);
        }
    }

    // merge 4 k-split partials in smem (pass 0 writes, 1-3 add)
    for (int s = 0; s < 4; s++) {
        __syncthreads();
        if (ksub == s) {
#pragma unroll
            for (int p = 0; p < 2; p++)
#pragma unroll
                for (int j = 0; j < 4; j++) {
                    float lo, hi; upk2(lo, hi, acc[p][j]);
                    int aa = a4 + 2 * p, dd = d4 + j;
                    if (s == 0) { S.accS[aa][dd] = lo; S.accS[aa + 1][dd] = hi; }
                    else        { S.accS[aa][dd] += lo; S.accS[aa + 1][dd] += hi; }
                }
        }
    }
    __syncthreads();
    for (int idx = tid; idx < 1024; idx += 256) {
        int aa = idx >> 5, dd = idx & 31;
        atomicAdd(&g_acc[(a0 + aa) * 32 + dd], S.accS[aa][dd]);
    }

    // ---- fused epilogue: last of the 32 blocks feeding this a-tile finishes it ----
    __threadfence();
    __shared__ int lastFlag;
    if (tid == 0) {
        int done = atomicAdd(&g_ctr[blockIdx.y], 1);
        lastFlag = (done == 31);
    }
    __syncthreads();
    if (lastFlag) {
        for (int idx = tid; idx < 1024; idx += 256) {
            int n = a0 + (idx >> 5), d = idx & 31;
            float acc = __ldcg(&g_acc[n * 32 + d]);
            const float* wb = g_XW2b + n * 512 + d;
            const float* wa = g_XW2a + n * 512 + d;
#pragma unroll
            for (int t = 0; t < 16; t++)
                acc += __ldcg(&g_r1[n * 16 + t]) * wb[t * 32]
                     + __ldcg(&g_c2[n * 16 + t]) * wa[t * 32];
            out[n * 32 + d] = fmaxf(acc, 0.2f * acc);
        }
    }
}

// ---------------- launch ----------------
extern "C" void kernel_launch(void* const* d_in, const int* in_sizes, int n_in,
                              void* d_out, int out_size) {
    const float* x   = (const float*)d_in[0];
    const float* adj = (const float*)d_in[1];
    const float* W1  = (const float*)d_in[2];
    const float* W2  = (const float*)d_in[3];
    const float* W3  = (const float*)d_in[4];
    float* out = (float*)d_out;
    (void)in_sizes; (void)n_in; (void)out_size;

    cudaFuncSetAttribute(k7_fused, cudaFuncAttributeMaxDynamicSharedMemorySize,
                         (int)sizeof(K7S));

    k1_precompute<<<128, 256>>>(x, W1, W2, W3);
    k2_logits<<<dim3(16, 16), 512>>>(adj);
    k5_softmax<<<1024, 256>>>();
    k7_fused<<<dim3(16, 16, 2), 256, sizeof(K7S)>>>(adj, out);
}

// round 7
// speedup vs baseline: 1.2567x; 1.0004x over previous
#include <cuda_runtime.h>

#define NN 512
#define TP 16

typedef unsigned long long ull;

// ---------- f32x2 packed helpers (FFMA2: 2x fp32 rate, only reachable via PTX) ----------
__device__ __forceinline__ ull pk2(float lo, float hi) {
    ull r; asm("mov.b64 %0, {%1, %2};" : "=l"(r) : "f"(lo), "f"(hi)); return r;
}
__device__ __forceinline__ void upk2(float& lo, float& hi, ull v) {
    asm("mov.b64 {%0, %1}, %2;" : "=f"(lo), "=f"(hi) : "l"(v));
}
__device__ __forceinline__ void ffma2(ull& acc, ull a, ull b) {
    asm("fma.rn.f32x2 %0, %1, %2, %0;" : "+l"(acc) : "l"(a), "l"(b));
}

// ---------------- scratch ----------------
__device__ float g_XW1a[NN * TP * 32];
__device__ float g_XW1b[NN * TP * 32];
__device__ float g_XW2a[NN * TP * 32];
__device__ float g_XW2b[NN * TP * 32];
__device__ float g_Q[NN * 32];
__device__ float g_QB[NN * TP];
__device__ float g_RA[NN * TP];
__device__ float g_L1[NN * NN];    // logits1 -> s1
__device__ float g_L2T[NN * NN];   // logits2^T -> s2^T
__device__ float g_r1[NN * TP];
__device__ float g_c2[NN * TP];
__device__ float g_acc[NN * 32];

// ---------------- k1: XW1a/b, XW2a/b, Q, QB, RA ----------------
__global__ void k1_precompute(const float* __restrict__ x,
                              const float* __restrict__ W1,
                              const float* __restrict__ W2,
                              const float* __restrict__ W3) {
    int n0 = blockIdx.x * 4;
    __shared__ float xs[4][16];
    int tid = threadIdx.x;
    if (tid < 64) xs[tid / 16][tid % 16] = x[(n0 + tid / 16) * 16 + (tid % 16)];
    __syncthreads();

    for (int th = tid; th < 512; th += 256) {
        float a1[4] = {0,0,0,0}, b1[4] = {0,0,0,0};
        float a2[4] = {0,0,0,0}, b2[4] = {0,0,0,0};
        for (int i = 0; i < 16; i++) {
            float w1a = W1[i * 512 + th];
            float w1b = W1[(i + 16) * 512 + th];
            float w2a = W2[i * 512 + th];
            float w2b = W2[(i + 16) * 512 + th];
#pragma unroll
            for (int j = 0; j < 4; j++) {
                float xv = xs[j][i];
                a1[j] += xv * w1a; b1[j] += xv * w1b;
                a2[j] += xv * w2a; b2[j] += xv * w2b;
            }
        }
#pragma unroll
        for (int j = 0; j < 4; j++) {
            g_XW1a[(n0 + j) * 512 + th] = a1[j];
            g_XW1b[(n0 + j) * 512 + th] = b1[j];
            g_XW2a[(n0 + j) * 512 + th] = a2[j];
            g_XW2b[(n0 + j) * 512 + th] = b2[j];
        }
    }
    if (tid < 32) {
#pragma unroll
        for (int j = 0; j < 4; j++) {
            float acc = 0.f;
            for (int i = 0; i < 16; i++) acc += xs[j][i] * W3[i * 32 + tid];
            g_Q[(n0 + j) * 32 + tid] = acc;
        }
    }
    __syncthreads();
    if (tid < 64) {
        int n = n0 + tid / 16, t = tid % 16;
        const float* q  = g_Q + n * 32;
        const float* wa = g_XW1a + n * 512 + t * 32;
        const float* wb = g_XW1b + n * 512 + t * 32;
        float ra = 0.f, qb = 0.f;
#pragma unroll
        for (int h = 0; h < 32; h++) { float qv = q[h]; ra += qv * wa[h]; qb += qv * wb[h]; }
        g_RA[n * 16 + t] = ra;
        g_QB[n * 16 + t] = qb;
    }
}

// ---------------- k2: fused logits + zero accumulators ----------------
__global__ void __launch_bounds__(512) k2_logits(const float* __restrict__ adj) {
    int tid = threadIdx.x;
    int bid = blockIdx.y * 16 + blockIdx.x;
    if (bid < 32)      g_acc[bid * 512 + tid] = 0.f;
    else if (bid < 48) g_r1[(bid - 32) * 512 + tid] = 0.f;
    else if (bid < 64) g_c2[(bid - 48) * 512 + tid] = 0.f;

    int a0 = blockIdx.y * 32, b0 = blockIdx.x * 32;
    int bl = tid >> 4, t = tid & 15;
    int bg = b0 + bl;

    __shared__ ull   Qs[32][16];
    __shared__ float QBs[32][16], RAs[32][16];
    {
        int a = tid >> 4, p = tid & 15;
        float2 v = *((const float2*)(g_Q + (a0 + a) * 32) + p);
        Qs[a][p]  = pk2(v.x, v.y);
        QBs[a][p] = g_QB[(a0 + a) * 16 + p];
        RAs[a][p] = g_RA[(a0 + a) * 16 + p];
    }
    ull wa[16], wb[16];
    {
        const float4* pa = (const float4*)(g_XW1a + (bg * 16 + t) * 32);
        const float4* pb = (const float4*)(g_XW1b + (bg * 16 + t) * 32);
#pragma unroll
        for (int v = 0; v < 8; v++) {
            float4 fa = pa[v], fb = pb[v];
            wa[2 * v] = pk2(fa.x, fa.y); wa[2 * v + 1] = pk2(fa.z, fa.w);
            wb[2 * v] = pk2(fb.x, fb.y); wb[2 * v + 1] = pk2(fb.z, fb.w);
        }
    }
    __syncthreads();

    bool hasT = (t < 15);
    const float* pR = adj + ((long)a0 * 512 + bg) * 15 + t;
    const float* pC = adj + ((long)bg * 512 + a0) * 15 + t;

    // software-pipelined adj loads (break LDG->use latency chain)
    float arN = 0.f, acN = 0.f;
    if (hasT) { arN = __ldg(pR); acN = __ldg(pC); }

    for (int al = 0; al < 32; al++) {
        float ar = arN, ac = acN;
        if (hasT && al < 31) {
            arN = __ldg(pR + (al + 1) * 7680);
            acN = __ldg(pC + (al + 1) * 15);
        }
        int ag = a0 + al;
        ull acc1 = 0ull, acc2 = 0ull;
        const ulonglong2* qrow = (const ulonglong2*)Qs[al];
#pragma unroll
        for (int j = 0; j < 8; j++) {
            ulonglong2 q = qrow[j];
            ffma2(acc1, q.x, wa[2 * j]);
            ffma2(acc1, q.y, wa[2 * j + 1]);
            ffma2(acc2, q.x, wb[2 * j]);
            ffma2(acc2, q.y, wb[2 * j + 1]);
        }
        float lo, hi;
        upk2(lo, hi, acc1); float p1 = lo + hi;
        upk2(lo, hi, acc2); float p2 = lo + hi;

        float l1p, l2p;
        if (hasT) {
            l1p = ar * p1 + ac * QBs[al][t];
            l2p = ac * RAs[al][t] + ar * p2;
        } else {
            bool dg = (ag == bg);
            l1p = dg ? (p1 + QBs[al][15]) : 0.f;
            l2p = dg ? (RAs[al][15] + p2) : 0.f;
        }
        // packed dual reduction: 5 shfl instead of 8
        float u = l1p + __shfl_xor_sync(0xffffffffu, l1p, 8);
        float v = l2p + __shfl_xor_sync(0xffffffffu, l2p, 8);
        float w = (t & 8) ? v : u;
        w += __shfl_xor_sync(0xffffffffu, w, 4);
        w += __shfl_xor_sync(0xffffffffu, w, 2);
        w += __shfl_xor_sync(0xffffffffu, w, 1);
        if (t == 0) g_L1[ag * 512 + bg]  = w;
        if (t == 8) g_L2T[ag * 512 + bg] = w;
    }
}

// ---------------- k5: row softmax ----------------
__global__ void k5_softmax() {
    int r = blockIdx.x;
    float* row = (r < 512) ? (g_L1 + r * 512) : (g_L2T + (r - 512) * 512);
    int tid = threadIdx.x;
    __shared__ float red[8];
    float v0 = row[tid], v1 = row[tid + 256];
    float m = fmaxf(v0, v1);
#pragma unroll
    for (int o = 16; o; o >>= 1) m = fmaxf(m, __shfl_xor_sync(0xffffffffu, m, o));
    if ((tid & 31) == 0) red[tid >> 5] = m;
    __syncthreads();
    float bm = red[0];
#pragma unroll
    for (int i = 1; i < 8; i++) bm = fmaxf(bm, red[i]);
    float e0 = __expf(v0 - bm), e1 = __expf(v1 - bm);
    float s = e0 + e1;
#pragma unroll
    for (int o = 16; o; o >>= 1) s += __shfl_xor_sync(0xffffffffu, s, o);
    __syncthreads();
    if ((tid & 31) == 0) red[tid >> 5] = s;
    __syncthreads();
    float bs = red[0] + red[1] + red[2] + red[3] + red[4] + red[5] + red[6] + red[7];
    float inv = 1.0f / bs;
    row[tid] = e0 * inv;
    row[tid + 256] = e1 * inv;
}

// ---------------- k7: split-variant fused A-build + 4a x 4d GEMM + transposed r1/c2 ----------------
// grid (16 m-tiles, 16 a-tiles, 2 variants), 256 threads.
// Block (bx,by,var) stages adjS = adj[rows a-tile(by), cols m-range(bx)].
// Reading adjS transposed gives exactly the data for the r1/c2 partial of
// a-tile bx over m-range by -> no strided global loads anywhere.
struct K7S {
    ull   Asp[128][16];    // packed a-pairs
    float Bs[128][32];
    float ss[32][33];      // s rows a-tile(by), cols m-range(bx)  (GEMM role)
    float ssT[32][33];     // s rows m-range(bx), cols a-tile(by)  (r1/c2 role)
    float adjS[32][121];
    float accS[32][33];
};

__global__ void __launch_bounds__(256) k7_fused(const float* __restrict__ adj) {
    extern __shared__ char smem_raw[];
    K7S& S = *reinterpret_cast<K7S*>(smem_raw);
    int m0 = blockIdx.x * 32;
    int a0 = blockIdx.y * 32;
    int var = blockIdx.z;
    int tid = threadIdx.x;

    const float* sSrc = var ? g_L2T : g_L1;
    const float* bSrc = var ? g_XW2b : g_XW2a;
    float* rcDst      = var ? g_c2 : g_r1;

#pragma unroll
    for (int j = 0; j < 4; j++) {
        int idx = tid + j * 256;
        int a = idx >> 5, ml = idx & 31;
        S.ss[a][ml]  = sSrc[(a0 + a) * 512 + m0 + ml];
        S.ssT[a][ml] = sSrc[(m0 + a) * 512 + a0 + ml];
    }
    __syncthreads();

    // diagonal slot t=15 of r1/c2 (each a-tile handled exactly once, by its diag block)
    if (m0 == a0 && tid < 32) {
        atomicAdd(&rcDst[(a0 + tid) * 16 + 15], S.ss[tid][tid]);
    }

    // thread tile: 4a x 4d, 4-way k-split within block
    int pos = tid & 63, ksub = tid >> 6;
    int a4 = (pos & 7) * 4;
    int d4 = (pos >> 3) * 4;
    ull acc[2][4];
#pragma unroll
    for (int p = 0; p < 2; p++)
#pragma unroll
        for (int j = 0; j < 4; j++) acc[p][j] = 0ull;

    // r1/c2 thread mapping (reused each chunk)
    int rcHalf = tid >> 7;            // i-range half: 0 -> 0..15, 1 -> 16..31
    int rcIdx  = tid & 127;
    int rcMl   = rcIdx >> 4, rcT = rcIdx & 15;

    for (int mc = 0; mc < 4; mc++) {
        int mb = m0 + mc * 8;
        __syncthreads();
        // stage adj rows: 32 a x 120 contiguous floats (coalesced)
        for (int idx = tid; idx < 960; idx += 256) {
            int a = idx / 30, r4 = (idx - a * 30) * 4;
            float4 v = *(const float4*)(adj + (long)(a0 + a) * 7680 + mb * 15 + r4);
            float* dst = &S.adjS[a][r4];
            dst[0] = v.x; dst[1] = v.y; dst[2] = v.z; dst[3] = v.w;
        }
        // stage B panel (float4)
        for (int idx = tid; idx < 1024; idx += 256) {
            int kk = idx >> 3, dd = (idx & 7) * 4;
            *(float4*)&S.Bs[kk][dd] = *(const float4*)(bSrc + (mb * 16 + kk) * 32 + dd);
        }
        __syncthreads();

        // transposed r1/c2 partial from staged adjS:
        // r1[mb+ml, t] += sum_i ssT[mc*8+ml][i] * adjS[i][ml*15+t]
        if (rcT < 15) {
            int i0 = rcHalf * 16;
            const float* sT = &S.ssT[mc * 8 + rcMl][i0];
            const float* aS = &S.adjS[i0][rcMl * 15 + rcT];
            float p = 0.f;
#pragma unroll
            for (int i = 0; i < 16; i++) p += sT[i] * aS[i * 121];
            atomicAdd(&rcDst[(mb + rcMl) * 16 + rcT], p);
        }

        // build packed A tile
#pragma unroll
        for (int j = 0; j < 8; j++) {
            int idx = tid + j * 256;
            int ap = idx & 15, kk = idx >> 4;
            int ml = kk >> 4, t = kk & 15;
            float v[2];
#pragma unroll
            for (int l = 0; l < 2; l++) {
                int a = 2 * ap + l;
                float sv = S.ss[a][mc * 8 + ml];
                if (t < 15) {
                    v[l] = sv * S.adjS[a][ml * 15 + t];
                } else {
                    v[l] = (mb + ml == a0 + a) ? sv : 0.f;
                }
            }
            S.Asp[kk][ap] = pk2(v[0], v[1]);
        }
        __syncthreads();
        // inner: 32 kk per thread
        int kk0 = ksub * 32;
        const ull*   pA = &S.Asp[0][(pos & 7) * 2];
        const float* pB = &S.Bs[0][d4];
#pragma unroll 8
        for (int kk = kk0; kk < kk0 + 32; kk++) {
            ulonglong2 A = *(const ulonglong2*)(pA + kk * 16);
            float4 b = *(const float4*)(pB + kk * 32);
            ull bx = pk2(b.x, b.x), by = pk2(b.y, b.y);
            ull bz = pk2(b.z, b.z), bw = pk2(b.w, b.w);
            ffma2(acc[0][0], A.x, bx); ffma2(acc[0][1], A.x, by);
            ffma2(acc[0][2], A.x, bz); ffma2(acc[0][3], A.x, bw);
            ffma2(acc[1][0], A.y, bx); ffma2(acc[1][1], A.y, by);
            ffma2(acc[1][2], A.y, bz); ffma2(acc[1][3], A.y, bw);
        }
    }

    // merge 4 k-split partials in smem (pass 0 writes, 1-3 add)
    for (int s = 0; s < 4; s++) {
        __syncthreads();
        if (ksub == s) {
#pragma unroll
            for (int p = 0; p < 2; p++)
#pragma unroll
                for (int j = 0; j < 4; j++) {
                    float lo, hi; upk2(lo, hi, acc[p][j]);
                    int aa = a4 + 2 * p, dd = d4 + j;
                    if (s == 0) { S.accS[aa][dd] = lo; S.accS[aa + 1][dd] = hi; }
                    else        { S.accS[aa][dd] += lo; S.accS[aa + 1][dd] += hi; }
                }
        }
    }
    __syncthreads();
    for (int idx = tid; idx < 1024; idx += 256) {
        int aa = idx >> 5, dd = idx & 31;
        atomicAdd(&g_acc[(a0 + aa) * 32 + dd], S.accS[aa][dd]);
    }
}

// ---------------- k7b: epilogue ----------------
__global__ void k7b_epilogue(float* __restrict__ out) {
    int idx = blockIdx.x * 256 + threadIdx.x;
    int n = idx >> 5, d = idx & 31;
    float acc = g_acc[idx];
    const float* r1 = g_r1 + n * 16;
    const float* c2 = g_c2 + n * 16;
    const float* wb = g_XW2b + n * 512 + d;
    const float* wa = g_XW2a + n * 512 + d;
#pragma unroll
    for (int t = 0; t < 16; t++) acc += r1[t] * wb[t * 32] + c2[t] * wa[t * 32];
    out[idx] = fmaxf(acc, 0.2f * acc);
}

// ---------------- launch ----------------
extern "C" void kernel_launch(void* const* d_in, const int* in_sizes, int n_in,
                              void* d_out, int out_size) {
    const float* x   = (const float*)d_in[0];
    const float* adj = (const float*)d_in[1];
    const float* W1  = (const float*)d_in[2];
    const float* W2  = (const float*)d_in[3];
    const float* W3  = (const float*)d_in[4];
    float* out = (float*)d_out;
    (void)in_sizes; (void)n_in; (void)out_size;

    cudaFuncSetAttribute(k7_fused, cudaFuncAttributeMaxDynamicSharedMemorySize,
                         (int)sizeof(K7S));

    k1_precompute<<<128, 256>>>(x, W1, W2, W3);
    k2_logits<<<dim3(16, 16), 512>>>(adj);
    k5_softmax<<<1024, 256>>>();
    k7_fused<<<dim3(16, 16, 2), 256, sizeof(K7S)>>>(adj);
    k7b_epilogue<<<64, 256>>>(out);
}

// round 8
// speedup vs baseline: 1.2605x; 1.0030x over previous
#include <cuda_runtime.h>

#define NN 512
#define TP 16

typedef unsigned long long ull;

// ---------- f32x2 packed helpers (FFMA2: 2x fp32 rate, only reachable via PTX) ----------
__device__ __forceinline__ ull pk2(float lo, float hi) {
    ull r; asm("mov.b64 %0, {%1, %2};" : "=l"(r) : "f"(lo), "f"(hi)); return r;
}
__device__ __forceinline__ void upk2(float& lo, float& hi, ull v) {
    asm("mov.b64 {%0, %1}, %2;" : "=f"(lo), "=f"(hi) : "l"(v));
}
__device__ __forceinline__ void ffma2(ull& acc, ull a, ull b) {
    asm("fma.rn.f32x2 %0, %1, %2, %0;" : "+l"(acc) : "l"(a), "l"(b));
}

// ---------------- scratch ----------------
__device__ float g_XW1a[NN * TP * 32];
__device__ float g_XW1b[NN * TP * 32];
__device__ float g_XW2a[NN * TP * 32];
__device__ float g_XW2b[NN * TP * 32];
__device__ float g_Q[NN * 32];
__device__ float g_QB[NN * TP];
__device__ float g_RA[NN * TP];
__device__ float g_L1[NN * NN];    // logits1 -> s1
__device__ float g_L2T[NN * NN];   // logits2^T -> s2^T
__device__ float g_r1[NN * TP];
__device__ float g_c2[NN * TP];
__device__ float g_acc[NN * 32];

// ---------------- k1: XW1a/b, XW2a/b, Q, QB, RA ----------------
__global__ void k1_precompute(const float* __restrict__ x,
                              const float* __restrict__ W1,
                              const float* __restrict__ W2,
                              const float* __restrict__ W3) {
    int n0 = blockIdx.x * 4;
    __shared__ float xs[4][16];
    int tid = threadIdx.x;
    if (tid < 64) xs[tid / 16][tid % 16] = x[(n0 + tid / 16) * 16 + (tid % 16)];
    __syncthreads();

    for (int th = tid; th < 512; th += 256) {
        float a1[4] = {0,0,0,0}, b1[4] = {0,0,0,0};
        float a2[4] = {0,0,0,0}, b2[4] = {0,0,0,0};
        for (int i = 0; i < 16; i++) {
            float w1a = W1[i * 512 + th];
            float w1b = W1[(i + 16) * 512 + th];
            float w2a = W2[i * 512 + th];
            float w2b = W2[(i + 16) * 512 + th];
#pragma unroll
            for (int j = 0; j < 4; j++) {
                float xv = xs[j][i];
                a1[j] += xv * w1a; b1[j] += xv * w1b;
                a2[j] += xv * w2a; b2[j] += xv * w2b;
            }
        }
#pragma unroll
        for (int j = 0; j < 4; j++) {
            g_XW1a[(n0 + j) * 512 + th] = a1[j];
            g_XW1b[(n0 + j) * 512 + th] = b1[j];
            g_XW2a[(n0 + j) * 512 + th] = a2[j];
            g_XW2b[(n0 + j) * 512 + th] = b2[j];
        }
    }
    if (tid < 32) {
#pragma unroll
        for (int j = 0; j < 4; j++) {
            float acc = 0.f;
            for (int i = 0; i < 16; i++) acc += xs[j][i] * W3[i * 32 + tid];
            g_Q[(n0 + j) * 32 + tid] = acc;
        }
    }
    __syncthreads();
    if (tid < 64) {
        int n = n0 + tid / 16, t = tid % 16;
        const float* q  = g_Q + n * 32;
        const float* wa = g_XW1a + n * 512 + t * 32;
        const float* wb = g_XW1b + n * 512 + t * 32;
        float ra = 0.f, qb = 0.f;
#pragma unroll
        for (int h = 0; h < 32; h++) { float qv = q[h]; ra += qv * wa[h]; qb += qv * wb[h]; }
        g_RA[n * 16 + t] = ra;
        g_QB[n * 16 + t] = qb;
    }
}

// ---------------- k2: fused logits + zero accumulators ----------------
__global__ void __launch_bounds__(512) k2_logits(const float* __restrict__ adj) {
    int tid = threadIdx.x;
    int bid = blockIdx.y * 16 + blockIdx.x;
    if (bid < 32)      g_acc[bid * 512 + tid] = 0.f;
    else if (bid < 48) g_r1[(bid - 32) * 512 + tid] = 0.f;
    else if (bid < 64) g_c2[(bid - 48) * 512 + tid] = 0.f;

    int a0 = blockIdx.y * 32, b0 = blockIdx.x * 32;
    int bl = tid >> 4, t = tid & 15;
    int bg = b0 + bl;

    __shared__ ull   Qs[32][16];
    __shared__ float QBs[32][16], RAs[32][16];
    {
        int a = tid >> 4, p = tid & 15;
        float2 v = *((const float2*)(g_Q + (a0 + a) * 32) + p);
        Qs[a][p]  = pk2(v.x, v.y);
        QBs[a][p] = g_QB[(a0 + a) * 16 + p];
        RAs[a][p] = g_RA[(a0 + a) * 16 + p];
    }
    ull wa[16], wb[16];
    {
        const float4* pa = (const float4*)(g_XW1a + (bg * 16 + t) * 32);
        const float4* pb = (const float4*)(g_XW1b + (bg * 16 + t) * 32);
#pragma unroll
        for (int v = 0; v < 8; v++) {
            float4 fa = pa[v], fb = pb[v];
            wa[2 * v] = pk2(fa.x, fa.y); wa[2 * v + 1] = pk2(fa.z, fa.w);
            wb[2 * v] = pk2(fb.x, fb.y); wb[2 * v + 1] = pk2(fb.z, fb.w);
        }
    }
    __syncthreads();

    bool hasT = (t < 15);
    const float* pR = adj + ((long)a0 * 512 + bg) * 15 + t;
    const float* pC = adj + ((long)bg * 512 + a0) * 15 + t;

    // software-pipelined adj loads (break LDG->use latency chain)
    float arN = 0.f, acN = 0.f;
    if (hasT) { arN = __ldg(pR); acN = __ldg(pC); }

    for (int al = 0; al < 32; al++) {
        float ar = arN, ac = acN;
        if (hasT && al < 31) {
            arN = __ldg(pR + (al + 1) * 7680);
            acN = __ldg(pC + (al + 1) * 15);
        }
        int ag = a0 + al;
        ull acc1 = 0ull, acc2 = 0ull;
        const ulonglong2* qrow = (const ulonglong2*)Qs[al];
#pragma unroll
        for (int j = 0; j < 8; j++) {
            ulonglong2 q = qrow[j];
            ffma2(acc1, q.x, wa[2 * j]);
            ffma2(acc1, q.y, wa[2 * j + 1]);
            ffma2(acc2, q.x, wb[2 * j]);
            ffma2(acc2, q.y, wb[2 * j + 1]);
        }
        float lo, hi;
        upk2(lo, hi, acc1); float p1 = lo + hi;
        upk2(lo, hi, acc2); float p2 = lo + hi;

        float l1p, l2p;
        if (hasT) {
            l1p = ar * p1 + ac * QBs[al][t];
            l2p = ac * RAs[al][t] + ar * p2;
        } else {
            bool dg = (ag == bg);
            l1p = dg ? (p1 + QBs[al][15]) : 0.f;
            l2p = dg ? (RAs[al][15] + p2) : 0.f;
        }
        // packed dual reduction: 5 shfl instead of 8
        float u = l1p + __shfl_xor_sync(0xffffffffu, l1p, 8);
        float v = l2p + __shfl_xor_sync(0xffffffffu, l2p, 8);
        float w = (t & 8) ? v : u;
        w += __shfl_xor_sync(0xffffffffu, w, 4);
        w += __shfl_xor_sync(0xffffffffu, w, 2);
        w += __shfl_xor_sync(0xffffffffu, w, 1);
        if (t == 0) g_L1[ag * 512 + bg]  = w;
        if (t == 8) g_L2T[ag * 512 + bg] = w;
    }
}

// ---------------- k5: row softmax ----------------
__global__ void k5_softmax() {
    int r = blockIdx.x;
    float* row = (r < 512) ? (g_L1 + r * 512) : (g_L2T + (r - 512) * 512);
    int tid = threadIdx.x;
    __shared__ float red[8];
    float v0 = row[tid], v1 = row[tid + 256];
    float m = fmaxf(v0, v1);
#pragma unroll
    for (int o = 16; o; o >>= 1) m = fmaxf(m, __shfl_xor_sync(0xffffffffu, m, o));
    if ((tid & 31) == 0) red[tid >> 5] = m;
    __syncthreads();
    float bm = red[0];
#pragma unroll
    for (int i = 1; i < 8; i++) bm = fmaxf(bm, red[i]);
    float e0 = __expf(v0 - bm), e1 = __expf(v1 - bm);
    float s = e0 + e1;
#pragma unroll
    for (int o = 16; o; o >>= 1) s += __shfl_xor_sync(0xffffffffu, s, o);
    __syncthreads();
    if ((tid & 31) == 0) red[tid >> 5] = s;
    __syncthreads();
    float bs = red[0] + red[1] + red[2] + red[3] + red[4] + red[5] + red[6] + red[7];
    float inv = 1.0f / bs;
    row[tid] = e0 * inv;
    row[tid + 256] = e1 * inv;
}

// ---------------- k7: high-occupancy split-variant A-build + 4a x 4d GEMM ----------------
// grid (32 m-tiles of 16, 16 a-tiles of 32, 2 variants) = 1024 blocks, 256 threads.
// Small smem (~34KB) -> 5-6 blocks/SM resident. B pre-duplicated as packed f32x2.
struct K7S {
    ull   Asp[64][16];     // packed a-pairs, per chunk (64 kk)          8KB
    ull   Bsp[64][32];     // B duplicated pairs (b,b) per d             16KB
    float ss[32][17];      // s[a-tile rows][m-range 16]                 2.2KB
    union {
        float adjS[32][61];   // per-chunk adj staging (4 m x 15 t)      7.8KB
        float accS[32][33];   // merge buffer (used after last chunk)
    } u;
};

__global__ void __launch_bounds__(256) k7_fused(const float* __restrict__ adj) {
    extern __shared__ char smem_raw[];
    K7S& S = *reinterpret_cast<K7S*>(smem_raw);
    int m0 = blockIdx.x * 16;
    int a0 = blockIdx.y * 32;
    int var = blockIdx.z;
    int tid = threadIdx.x;

    const float* sSrc = var ? g_L2T : g_L1;
    const float* bSrc = var ? g_XW2b : g_XW2a;
    float* rcDst      = var ? g_c2 : g_r1;

#pragma unroll
    for (int j = 0; j < 2; j++) {
        int idx = tid + j * 256;
        int a = idx >> 4, ml = idx & 15;
        S.ss[a][ml] = sSrc[(a0 + a) * 512 + m0 + ml];
    }
    __syncthreads();

    // r1/c2 partials over this block's 16-m range (R4-style strided loads)
    {
        int a = tid >> 3, tp = tid & 7;
        int t0 = tp * 2;
        int ag = a0 + a;
        bool hasT1 = (t0 + 1 < 15);
        float r0 = 0.f, r1v = 0.f;
        for (int ml = 0; ml < 16; ml++) {
            const float* base = adj + ((long)(m0 + ml) * 512 + ag) * 15;
            float v0 = base[t0];
            float v1 = hasT1 ? base[t0 + 1] : 0.f;
            float w = S.ss[a][ml];
            r0 += w * v0; r1v += w * v1;
        }
        atomicAdd(&rcDst[ag * 16 + t0], r0);
        if (hasT1) {
            atomicAdd(&rcDst[ag * 16 + t0 + 1], r1v);
        } else if (ag >= m0 && ag < m0 + 16) {   // diag slot t=15, exactly once per a
            atomicAdd(&rcDst[ag * 16 + 15], S.ss[a][ag - m0]);
        }
    }

    // thread tile: 4a x 4d, 4-way k-split within block
    int pos = tid & 63, ksub = tid >> 6;
    int pa = (pos & 7) * 2;        // A-pair column (covers a = 2pa .. 2pa+3)
    int d4 = (pos >> 3) * 4;       // d base
    ull acc[2][4];
#pragma unroll
    for (int p = 0; p < 2; p++)
#pragma unroll
        for (int j = 0; j < 4; j++) acc[p][j] = 0ull;

    for (int mc = 0; mc < 4; mc++) {
        int mb = m0 + mc * 4;       // 4 m per chunk -> 64 kk
        int kbase = mb * 16;
        __syncthreads();
        // stage adj rows: 32 a x 60 contiguous floats (coalesced, 16B-aligned)
        for (int idx = tid; idx < 480; idx += 256) {
            int a = idx / 15, r4 = (idx % 15) * 4;
            float4 v = *(const float4*)(adj + (long)(a0 + a) * 7680 + mb * 15 + r4);
            float* dst = &S.u.adjS[a][r4];
            dst[0] = v.x; dst[1] = v.y; dst[2] = v.z; dst[3] = v.w;
        }
        // stage B panel duplicated: Bsp[kk][d] = (b,b)
        for (int idx = tid; idx < 512; idx += 256) {
            int kk = idx >> 3, dd = (idx & 7) * 4;
            float4 b = *(const float4*)(bSrc + (kbase + kk) * 32 + dd);
            ulonglong2 w0, w1;
            w0.x = pk2(b.x, b.x); w0.y = pk2(b.y, b.y);
            w1.x = pk2(b.z, b.z); w1.y = pk2(b.w, b.w);
            *(ulonglong2*)&S.Bsp[kk][dd]     = w0;
            *(ulonglong2*)&S.Bsp[kk][dd + 2] = w1;
        }
        __syncthreads();
        // build packed A tile (64 kk x 16 pairs)
#pragma unroll
        for (int j = 0; j < 4; j++) {
            int idx = tid + j * 256;
            int ap = idx & 15, kk = idx >> 4;
            int ml = kk >> 4, t = kk & 15;
            float v[2];
#pragma unroll
            for (int l = 0; l < 2; l++) {
                int a = 2 * ap + l;
                float sv = S.ss[a][mc * 4 + ml];
                if (t < 15) {
                    v[l] = sv * S.u.adjS[a][ml * 15 + t];
                } else {
                    v[l] = (mb + ml == a0 + a) ? sv : 0.f;
                }
            }
            S.Asp[kk][ap] = pk2(v[0], v[1]);
        }
        __syncthreads();
        // inner: 16 kk per thread, 11 instr / 16 FMA-pairs
        int kk0 = ksub * 16;
        const ull* pA = &S.Asp[kk0][pa];
        const ull* pB = &S.Bsp[kk0][d4];
#pragma unroll
        for (int i = 0; i < 16; i++) {
            ulonglong2 A  = *(const ulonglong2*)(pA + i * 16);
            ulonglong2 B0 = *(const ulonglong2*)(pB + i * 32);
            ulonglong2 B1 = *(const ulonglong2*)(pB + i * 32 + 2);
            ffma2(acc[0][0], A.x, B0.x); ffma2(acc[0][1], A.x, B0.y);
            ffma2(acc[0][2], A.x, B1.x); ffma2(acc[0][3], A.x, B1.y);
            ffma2(acc[1][0], A.y, B0.x); ffma2(acc[1][1], A.y, B0.y);
            ffma2(acc[1][2], A.y, B1.x); ffma2(acc[1][3], A.y, B1.y);
        }
    }

    // merge 4 k-split partials in smem (pass 0 writes, 1-3 add)
    for (int s = 0; s < 4; s++) {
        __syncthreads();
        if (ksub == s) {
#pragma unroll
            for (int p = 0; p < 2; p++)
#pragma unroll
                for (int j = 0; j < 4; j++) {
                    float lo, hi; upk2(lo, hi, acc[p][j]);
                    int aa = 2 * pa + 2 * p, dd = d4 + j;
                    if (s == 0) { S.u.accS[aa][dd] = lo; S.u.accS[aa + 1][dd] = hi; }
                    else        { S.u.accS[aa][dd] += lo; S.u.accS[aa + 1][dd] += hi; }
                }
        }
    }
    __syncthreads();
    for (int idx = tid; idx < 1024; idx += 256) {
        int aa = idx >> 5, dd = idx & 31;
        atomicAdd(&g_acc[(a0 + aa) * 32 + dd], S.u.accS[aa][dd]);
    }
}

// ---------------- k7b: epilogue ----------------
__global__ void k7b_epilogue(float* __restrict__ out) {
    int idx = blockIdx.x * 256 + threadIdx.x;
    int n = idx >> 5, d = idx & 31;
    float acc = g_acc[idx];
    const float* r1 = g_r1 + n * 16;
    const float* c2 = g_c2 + n * 16;
    const float* wb = g_XW2b + n * 512 + d;
    const float* wa = g_XW2a + n * 512 + d;
#pragma unroll
    for (int t = 0; t < 16; t++) acc += r1[t] * wb[t * 32] + c2[t] * wa[t * 32];
    out[idx] = fmaxf(acc, 0.2f * acc);
}

// ---------------- launch ----------------
extern "C" void kernel_launch(void* const* d_in, const int* in_sizes, int n_in,
                              void* d_out, int out_size) {
    const float* x   = (const float*)d_in[0];
    const float* adj = (const float*)d_in[1];
    const float* W1  = (const float*)d_in[2];
    const float* W2  = (const float*)d_in[3];
    const float* W3  = (const float*)d_in[4];
    float* out = (float*)d_out;
    (void)in_sizes; (void)n_in; (void)out_size;

    cudaFuncSetAttribute(k7_fused, cudaFuncAttributeMaxDynamicSharedMemorySize,
                         (int)sizeof(K7S));

    k1_precompute<<<128, 256>>>(x, W1, W2, W3);
    k2_logits<<<dim3(16, 16), 512>>>(adj);
    k5_softmax<<<1024, 256>>>();
    k7_fused<<<dim3(32, 16, 2), 256, sizeof(K7S)>>>(adj);
    k7b_epilogue<<<64, 256>>>(out);
}